// round 4
// baseline (speedup 1.0000x reference)
#include <cuda_runtime.h>
#include <cuda_fp16.h>
#include <cstdint>

// ---------------------------------------------------------------------------
// Problem constants
// ---------------------------------------------------------------------------
#define BATCH        2048
#define IN_FEAT      4096
#define OUT_FEAT     4096
#define BLOCK        32
#define NNZ          2048
#define N_ROW_BLOCKS 128
#define MTILE        128                    // batch rows per CTA
#define N_BATCH_TILES (BATCH / MTILE)       // 16

// ---------------------------------------------------------------------------
// Device scratch (__device__ globals only; no runtime allocation)
// ---------------------------------------------------------------------------
__device__ __align__(256) __half g_xh[BATCH * IN_FEAT];     // 16 MB
__device__ __align__(256) __half g_wh[NNZ * BLOCK * BLOCK]; // 4 MB
__device__ int g_cnt[N_ROW_BLOCKS];
__device__ int g_off[N_ROW_BLOCKS];
__device__ int g_list[NNZ];   // packed: (col << 16) | nnz_index, ordered by n

// ---------------------------------------------------------------------------
// Helpers
// ---------------------------------------------------------------------------
__device__ __forceinline__ uint32_t smem_u32(const void* p) {
    uint32_t a;
    asm("{ .reg .u64 t; cvta.to.shared.u64 t, %1; cvt.u32.u64 %0, t; }"
        : "=r"(a) : "l"(p));
    return a;
}

// SW128-style swizzle over 128B-pitch rows: XOR bits [6:4] with bits [9:7].
// Makes ldmatrix (8 rows x 16B per phase) bank-conflict-free.
#define SW(o) ((o) ^ (((o) >> 3) & 0x70))

#define CP_ASYNC16(dst, src) \
    asm volatile("cp.async.cg.shared.global [%0], [%1], 16;" \
                 :: "r"(dst), "l"(src) : "memory")
#define CP_COMMIT() asm volatile("cp.async.commit_group;" ::: "memory")
#define CP_WAIT1()  asm volatile("cp.async.wait_group 1;" ::: "memory")

__device__ __forceinline__ void ldsm_x4(uint32_t* r, uint32_t addr) {
    asm volatile("ldmatrix.sync.aligned.m8n8.x4.shared.b16 {%0,%1,%2,%3}, [%4];"
                 : "=r"(r[0]), "=r"(r[1]), "=r"(r[2]), "=r"(r[3])
                 : "r"(addr));
}

__device__ __forceinline__ void mma_16816(float* d, const uint32_t* a,
                                          const uint32_t* b) {
    asm volatile(
        "mma.sync.aligned.m16n8k16.row.col.f32.f16.f16.f32 "
        "{%0,%1,%2,%3}, {%4,%5,%6,%7}, {%8,%9}, {%0,%1,%2,%3};"
        : "+f"(d[0]), "+f"(d[1]), "+f"(d[2]), "+f"(d[3])
        : "r"(a[0]), "r"(a[1]), "r"(a[2]), "r"(a[3]), "r"(b[0]), "r"(b[1]));
}

// ---------------------------------------------------------------------------
// fp32 -> fp16 conversion (exact grids)
// ---------------------------------------------------------------------------
__global__ void cvt_x_kernel(const float* __restrict__ src) {
    int i = blockIdx.x * blockDim.x + threadIdx.x;   // over float4
    float4 v = reinterpret_cast<const float4*>(src)[i];
    __half2* d = reinterpret_cast<__half2*>(g_xh);
    d[2 * i]     = __floats2half2_rn(v.x, v.y);
    d[2 * i + 1] = __floats2half2_rn(v.z, v.w);
}

__global__ void cvt_w_kernel(const float* __restrict__ src) {
    int i = blockIdx.x * blockDim.x + threadIdx.x;
    float4 v = reinterpret_cast<const float4*>(src)[i];
    __half2* d = reinterpret_cast<__half2*>(g_wh);
    d[2 * i]     = __floats2half2_rn(v.x, v.y);
    d[2 * i + 1] = __floats2half2_rn(v.z, v.w);
}

// ---------------------------------------------------------------------------
// CSR build: deterministic (ordered by n), warp-per-row.
// ---------------------------------------------------------------------------
__global__ void csr_count_kernel(const int* __restrict__ rows) {
    int wid = (blockIdx.x * blockDim.x + threadIdx.x) >> 5;   // 0..127
    int lid = threadIdx.x & 31;
    int cnt = 0;
    for (int n0 = 0; n0 < NNZ; n0 += 32) {
        int v = rows[n0 + lid];
        unsigned m = __ballot_sync(0xffffffffu, v == wid);
        cnt += __popc(m);
    }
    if (lid == 0) g_cnt[wid] = cnt;
}

__global__ void csr_prefix_kernel() {
    int r = threadIdx.x;           // 0..127
    __shared__ int s[N_ROW_BLOCKS];
    s[r] = g_cnt[r];
    __syncthreads();
    int o = 0;
    for (int i = 0; i < r; i++) o += s[i];
    g_off[r] = o;
}

__global__ void csr_scatter_kernel(const int* __restrict__ rows,
                                   const int* __restrict__ cols) {
    int wid = (blockIdx.x * blockDim.x + threadIdx.x) >> 5;   // row 0..127
    int lid = threadIdx.x & 31;
    int pos = g_off[wid];
    for (int n0 = 0; n0 < NNZ; n0 += 32) {
        int n = n0 + lid;
        int v = rows[n];
        unsigned m = __ballot_sync(0xffffffffu, v == wid);
        if (v == wid) {
            int p = pos + __popc(m & ((1u << lid) - 1));
            g_list[p] = (cols[n] << 16) | n;
        }
        pos += __popc(m);
    }
}

// ---------------------------------------------------------------------------
// Main block-sparse GEMM. Grid (128 row-blocks, 16 batch-tiles), 128 threads.
// Per nnz block: A = x tile [128 x 32] fp16, B = w block [32 x 32] fp16
// (row n, col k — exactly the col-major B that mma row.col expects).
// Double-buffered SMEM via cp.async; fp32 accumulators in registers.
// ---------------------------------------------------------------------------
#define A_BYTES (MTILE * 128)   // 16384 per buffer (128B pitch, swizzled)
#define B_BYTES (BLOCK * 128)   // 4096  per buffer

__device__ __forceinline__ void issue_loads(uint32_t sA, uint32_t sB,
                                            int tid, int batch0, int packed) {
    const int c   = packed >> 16;
    const int idx = packed & 0xffff;
    const char* xs = reinterpret_cast<const char*>(
        g_xh + (size_t)(batch0 + tid) * IN_FEAT + c * BLOCK);
#pragma unroll
    for (int i = 0; i < 4; i++) {
        CP_ASYNC16(sA + SW((uint32_t)tid * 128 + i * 16), xs + i * 16);
    }
    const int wr = tid >> 2, wi = tid & 3;
    const char* ws = reinterpret_cast<const char*>(
        g_wh + (size_t)idx * (BLOCK * BLOCK) + wr * BLOCK + wi * 8);
    CP_ASYNC16(sB + SW((uint32_t)wr * 128 + wi * 16), ws);
}

__global__ void __launch_bounds__(128)
bsd_main_kernel(float* __restrict__ out) {
    __shared__ __align__(1024) char sbuf[2 * A_BYTES + 2 * B_BYTES];

    const int r      = blockIdx.x;
    const int batch0 = blockIdx.y * MTILE;
    const int tid = threadIdx.x;
    const int wid = tid >> 5;
    const int lid = tid & 31;

    const uint32_t sb = smem_u32(sbuf);
    const int cnt = g_cnt[r];
    const int off = g_off[r];

    float acc[2][4][4];
#pragma unroll
    for (int mi = 0; mi < 2; mi++)
#pragma unroll
        for (int nj = 0; nj < 4; nj++)
#pragma unroll
            for (int k = 0; k < 4; k++) acc[mi][nj][k] = 0.f;

    // Prologue: fill both pipeline stages (always commit to keep group count fixed)
    if (cnt > 0) issue_loads(sb, sb + 2 * A_BYTES, tid, batch0, g_list[off]);
    CP_COMMIT();
    if (cnt > 1) issue_loads(sb + A_BYTES, sb + 2 * A_BYTES + B_BYTES,
                             tid, batch0, g_list[off + 1]);
    CP_COMMIT();

    const int mbase = wid * 32;

    for (int it = 0; it < cnt; ++it) {
        const int buf = it & 1;
        CP_WAIT1();
        __syncthreads();

        const uint32_t sA = sb + buf * A_BYTES;
        const uint32_t sB = sb + 2 * A_BYTES + buf * B_BYTES;

        // --- ldmatrix A: [mi][ki][4] ---
        uint32_t afrag[2][2][4];
#pragma unroll
        for (int mi = 0; mi < 2; mi++)
#pragma unroll
            for (int ki = 0; ki < 2; ki++) {
                uint32_t row = (uint32_t)(mbase + mi * 16 + (lid & 15));
                uint32_t kb  = (uint32_t)(ki * 32 + ((lid >> 4) * 16));
                ldsm_x4(afrag[mi][ki], sA + SW(row * 128 + kb));
            }
        // --- ldmatrix B: [ki][nj][2] (two n-tiles per x4) ---
        uint32_t bfrag[2][4][2];
#pragma unroll
        for (int ki = 0; ki < 2; ki++)
#pragma unroll
            for (int p = 0; p < 2; p++) {
                uint32_t n  = (uint32_t)(p * 16 + ((lid >> 4) * 8) + (lid & 7));
                uint32_t kb = (uint32_t)(ki * 32 + (((lid >> 3) & 1) * 16));
                uint32_t t[4];
                ldsm_x4(t, sB + SW(n * 128 + kb));
                bfrag[ki][2 * p + 0][0] = t[0];
                bfrag[ki][2 * p + 0][1] = t[1];
                bfrag[ki][2 * p + 1][0] = t[2];
                bfrag[ki][2 * p + 1][1] = t[3];
            }

        __syncthreads();   // everyone finished reading buf before refill

        if (it + 2 < cnt)
            issue_loads(sA, sB, tid, batch0, g_list[off + it + 2]);
        CP_COMMIT();

        // --- 16 MMAs ---
#pragma unroll
        for (int mi = 0; mi < 2; mi++)
#pragma unroll
            for (int nj = 0; nj < 4; nj++)
#pragma unroll
                for (int ki = 0; ki < 2; ki++)
                    mma_16816(acc[mi][nj], afrag[mi][ki], bfrag[ki][nj]);
    }

    // Epilogue: D fragment layout -> global.
    const int g = lid >> 2, t = lid & 3;
#pragma unroll
    for (int mi = 0; mi < 2; mi++) {
#pragma unroll
        for (int nj = 0; nj < 4; nj++) {
            const int row = batch0 + mbase + mi * 16 + g;
            const int col = r * BLOCK + nj * 8 + 2 * t;
            float2* p0 = reinterpret_cast<float2*>(out + (size_t)row * OUT_FEAT + col);
            float2* p1 = reinterpret_cast<float2*>(out + (size_t)(row + 8) * OUT_FEAT + col);
            *p0 = make_float2(acc[mi][nj][0], acc[mi][nj][1]);
            *p1 = make_float2(acc[mi][nj][2], acc[mi][nj][3]);
        }
    }
}

// ---------------------------------------------------------------------------
// Launch
// ---------------------------------------------------------------------------
extern "C" void kernel_launch(void* const* d_in, const int* in_sizes, int n_in,
                              void* d_out, int out_size) {
    (void)in_sizes; (void)n_in; (void)out_size;
    const float* x    = (const float*)d_in[0];   // [2048, 4096] fp32
    const float* w    = (const float*)d_in[1];   // [2048, 32, 32] fp32
    const int*   rows = (const int*)d_in[2];     // [2048] int32
    const int*   cols = (const int*)d_in[3];     // [2048] int32
    float*       out  = (float*)d_out;           // [2048, 4096] fp32

    cvt_x_kernel<<<(BATCH * IN_FEAT / 4) / 256, 256>>>(x);
    cvt_w_kernel<<<(NNZ * BLOCK * BLOCK / 4) / 256, 256>>>(w);
    csr_count_kernel<<<4, 1024>>>(rows);
    csr_prefix_kernel<<<1, N_ROW_BLOCKS>>>();
    csr_scatter_kernel<<<4, 1024>>>(rows, cols);

    dim3 grid(N_ROW_BLOCKS, N_BATCH_TILES);
    bsd_main_kernel<<<grid, 128>>>(out);
}